// round 9
// baseline (speedup 1.0000x reference)
#include <cuda_runtime.h>
#include <math.h>

#define T_LEN 512
#define B_SZ  64
#define D_SZ  1024
#define H_SZ  512
#define L_SZ  5

#define NCTA 128
#define NTHR 256

// ---------------- device-global scratch ----------------------------------------
__device__ float    g_XHt[T_LEN * H_SZ * B_SZ];   // [t][j][b]
__device__ float    g_XCt[T_LEN * H_SZ * B_SZ];   // [t][j][b]
__device__ float    g_h[2][H_SZ * B_SZ];          // hidden double buffer [j][b]
__device__ float    g_part[2][4][H_SZ][B_SZ];     // [gate][kg][j][b]
__device__ unsigned g_grp[8 * 64];                // 8 counters, 256B apart
__device__ unsigned g_root;
__device__ unsigned g_rel;

// Hierarchical grid barrier. ALL generations self-derived from tickets
// (monotonic, graph-replay safe, no external phase => no R7 deadlock class).
// acq_rel RMWs build the happens-before chain (CG grid.sync pattern);
// NO __threadfence => no CCTL.IVALL => weights stay L1-resident.
// Only thread 0 per CTA touches global sync state.
__device__ __forceinline__ void gbar(int tid, int cta) {
    __syncthreads();
    if (tid == 0) {
        unsigned t0;
        asm volatile("atom.acq_rel.gpu.global.add.u32 %0, [%1], 1;"
                     : "=r"(t0) : "l"(&g_grp[(cta & 7) * 64]) : "memory");
        unsigned gen = (t0 >> 4) + 1u;          // 16 arrivals per group
        if ((t0 & 15u) == 15u) {
            unsigned t1;
            asm volatile("atom.acq_rel.gpu.global.add.u32 %0, [%1], 1;"
                         : "=r"(t1) : "l"(&g_root) : "memory");
            if ((t1 & 7u) == 7u) {
                asm volatile("st.release.gpu.global.u32 [%0], %1;"
                             :: "l"(&g_rel), "r"((t1 >> 3) + 1u) : "memory");
            }
        }
        unsigned v;
        do {
            asm volatile("ld.acquire.gpu.global.u32 %0, [%1];"
                         : "=r"(v) : "l"(&g_rel) : "memory");
        } while ((int)(v - gen) < 0);
    }
    __syncthreads();
}

// ---------------- precompute: XHt/XCt[t][j][b] = x[t,b,:]@W[:,j] + bias[j] ------
__global__ void __launch_bounds__(NTHR) proj_kernel(
    const float* __restrict__ x,
    const float* __restrict__ Ww,
    const float* __restrict__ Wb,
    const int gate)
{
    __shared__ float As[32][128];
    __shared__ float Bs[32][64];
    float* __restrict__ dst = gate ? g_XCt : g_XHt;

    const int tid = threadIdx.x;
    const int bm  = blockIdx.x * 128;
    const int bn  = blockIdx.y * 64;
    const int tm  = tid & 15;
    const int tn  = tid >> 4;

    float acc[8][4];
#pragma unroll
    for (int i = 0; i < 8; i++)
#pragma unroll
        for (int j = 0; j < 4; j++) acc[i][j] = 0.0f;

    for (int k0 = 0; k0 < D_SZ; k0 += 32) {
#pragma unroll
        for (int r = 0; r < 4; r++) {
            int lin = tid + r * 256;
            int m = lin >> 3, kq = lin & 7;
            float4 v = *(const float4*)(x + (size_t)(bm + m) * D_SZ + k0 + kq * 4);
            As[kq * 4 + 0][m] = v.x;
            As[kq * 4 + 1][m] = v.y;
            As[kq * 4 + 2][m] = v.z;
            As[kq * 4 + 3][m] = v.w;
        }
#pragma unroll
        for (int r = 0; r < 2; r++) {
            int lin = tid + r * 256;
            int kk = lin >> 4, jq = lin & 15;
            *(float4*)&Bs[kk][jq * 4] =
                *(const float4*)(Ww + (size_t)(k0 + kk) * H_SZ + bn + jq * 4);
        }
        __syncthreads();
#pragma unroll
        for (int k = 0; k < 32; k++) {
            float4 a0 = *(const float4*)&As[k][tm * 4];
            float4 a1 = *(const float4*)&As[k][64 + tm * 4];
            float4 bv = *(const float4*)&Bs[k][tn * 4];
            float av[8] = {a0.x, a0.y, a0.z, a0.w, a1.x, a1.y, a1.z, a1.w};
            float bw[4] = {bv.x, bv.y, bv.z, bv.w};
#pragma unroll
            for (int i = 0; i < 8; i++)
#pragma unroll
                for (int j = 0; j < 4; j++)
                    acc[i][j] = fmaf(av[i], bw[j], acc[i][j]);
        }
        __syncthreads();
    }

#pragma unroll
    for (int i = 0; i < 8; i++) {
        int m = bm + ((i < 4) ? (tm * 4 + i) : (64 + tm * 4 + i - 4));
        int t = m >> 6, b = m & 63;
#pragma unroll
        for (int j = 0; j < 4; j++) {
            int jj = bn + tn * 4 + j;
            dst[(size_t)t * (H_SZ * B_SZ) + (size_t)jj * B_SZ + b] = acc[i][j] + Wb[jj];
        }
    }
}

// ---------------- persistent sequential kernel (R2 structure) -------------------
// Phase A: 128 CTAs = 32 jg x 4 kg; CTA tile = 64b x 16j x 128k x 2 gates.
//   Weights (80KB/CTA across 5 layers) are L1-resident (no fence flushes).
// Phase B: 1 element/thread; __expf activations.
__global__ void __launch_bounds__(NTHR, 1) rhn_seq_kernel(
    const float* __restrict__ RHw, const float* __restrict__ RHb,
    const float* __restrict__ RCw, const float* __restrict__ RCb,
    float* __restrict__ out)
{
    const int tid = threadIdx.x;
    const int cta = blockIdx.x;

    __shared__ __align__(16) float hs[32][64];      // [k][b]
    __shared__ __align__(16) float rhs_s[32][16];   // [k][j]
    __shared__ __align__(16) float rcs_s[32][16];   // [k][j]

    __stcg(&g_h[0][cta * NTHR + tid], 0.0f);

    const int jx  = tid & 15;
    const int byq = tid >> 4;
    const int jg  = cta & 31;
    const int kg  = cta >> 5;
    const int j0  = jg * 16;
    const int k0  = kg * 128;

    const int kk_r = tid >> 3, jq_r = tid & 7;

    const int e  = cta * NTHR + tid;  // phase-B element
    const int eb = e & 63;
    const int ej = e >> 6;

    // biases constant across run
    float bHr[L_SZ], bCr[L_SZ];
#pragma unroll
    for (int l = 0; l < L_SZ; l++) {
        bHr[l] = RHb[l * H_SZ + ej];
        bCr[l] = RCb[l * H_SZ + ej];
    }

    gbar(tid, cta);

    int p = 0;
    for (int pass = 0; pass < 2; pass++)
    for (int t = 0; t < T_LEN; t++)
    for (int l = 0; l < L_SZ; l++) {
        const float* __restrict__ Rh = RHw + (size_t)l * H_SZ * H_SZ;
        const float* __restrict__ Rc = RCw + (size_t)l * H_SZ * H_SZ;
        const float* __restrict__ hp = g_h[p];

        float aH0 = 0, aH1 = 0, aH2 = 0, aH3 = 0;
        float aC0 = 0, aC1 = 0, aC2 = 0, aC3 = 0;

        // prefetch chunk 0 (hidden via L2; weights via L1-resident plain loads)
        float4 h0v, h1v;
        float2 r0v, r1v;
        {
            const float4* h4 = (const float4*)(hp + k0 * 64);
            h0v = __ldcg(h4 + tid);
            h1v = __ldcg(h4 + tid + 256);
            r0v = *(const float2*)(Rh + (size_t)(k0 + kk_r) * H_SZ + j0 + 2 * jq_r);
            r1v = *(const float2*)(Rc + (size_t)(k0 + kk_r) * H_SZ + j0 + 2 * jq_r);
        }
#pragma unroll
        for (int c = 0; c < 4; c++) {
            __syncthreads();
            ((float4*)hs)[tid]       = h0v;
            ((float4*)hs)[tid + 256] = h1v;
            ((float2*)rhs_s)[tid]    = r0v;
            ((float2*)rcs_s)[tid]    = r1v;
            __syncthreads();
            if (c < 3) {
                int kb = k0 + (c + 1) * 32;
                const float4* h4 = (const float4*)(hp + kb * 64);
                h0v = __ldcg(h4 + tid);
                h1v = __ldcg(h4 + tid + 256);
                r0v = *(const float2*)(Rh + (size_t)(kb + kk_r) * H_SZ + j0 + 2 * jq_r);
                r1v = *(const float2*)(Rc + (size_t)(kb + kk_r) * H_SZ + j0 + 2 * jq_r);
            }
#pragma unroll
            for (int kk = 0; kk < 32; kk++) {
                float rh = rhs_s[kk][jx];
                float rc = rcs_s[kk][jx];
                float4 hv = *(const float4*)&hs[kk][byq * 4];
                aH0 = fmaf(hv.x, rh, aH0); aH1 = fmaf(hv.y, rh, aH1);
                aH2 = fmaf(hv.z, rh, aH2); aH3 = fmaf(hv.w, rh, aH3);
                aC0 = fmaf(hv.x, rc, aC0); aC1 = fmaf(hv.y, rc, aC1);
                aC2 = fmaf(hv.z, rc, aC2); aC3 = fmaf(hv.w, rc, aC3);
            }
        }
        __stcg((float4*)&g_part[0][kg][j0 + jx][byq * 4],
               make_float4(aH0, aH1, aH2, aH3));
        __stcg((float4*)&g_part[1][kg][j0 + jx][byq * 4],
               make_float4(aC0, aC1, aC2, aC3));
        gbar(tid, cta);

        // ---- phase B: reduce + activations + highway combine ----
        {
            float sH = __ldcg(&g_part[0][0][ej][eb]) + __ldcg(&g_part[0][1][ej][eb])
                     + __ldcg(&g_part[0][2][ej][eb]) + __ldcg(&g_part[0][3][ej][eb]);
            float sC = __ldcg(&g_part[1][0][ej][eb]) + __ldcg(&g_part[1][1][ej][eb])
                     + __ldcg(&g_part[1][2][ej][eb]) + __ldcg(&g_part[1][3][ej][eb]);
            sH += bHr[l];
            sC += bCr[l];
            if (l == 0) {
                sH += g_XHt[(size_t)t * (H_SZ * B_SZ) + e];
                sC += g_XCt[(size_t)t * (H_SZ * B_SZ) + e];
            }
            float hold = __ldcg(&g_h[p][e]);
            float hl = 1.0f - 2.0f / (1.0f + __expf(2.0f * sH));   // tanh
            float tl = 1.0f / (1.0f + __expf(-sC));                // sigmoid
            float hn = fmaf(tl, hl - hold, hold);
            __stcg(&g_h[p ^ 1][e], hn);
            if (l == L_SZ - 1) {
                size_t o = (size_t)t * (B_SZ * 2 * H_SZ) + (size_t)eb * (2 * H_SZ)
                         + (size_t)pass * H_SZ + ej;
                out[o] = hn;
                if (t == T_LEN - 1) {
                    out[(size_t)T_LEN * (B_SZ * 2 * H_SZ) + (size_t)eb * (2 * H_SZ)
                        + (size_t)pass * H_SZ + ej] = hn;
                }
            }
        }
        gbar(tid, cta);
        p ^= 1;
    }
}

extern "C" void kernel_launch(void* const* d_in, const int* in_sizes, int n_in,
                              void* d_out, int out_size)
{
    const float* x   = (const float*)d_in[0];
    const float* WHw = (const float*)d_in[1];
    const float* WHb = (const float*)d_in[2];
    const float* WCw = (const float*)d_in[3];
    const float* WCb = (const float*)d_in[4];
    const float* RHw = (const float*)d_in[5];
    const float* RHb = (const float*)d_in[6];
    const float* RCw = (const float*)d_in[7];
    const float* RCb = (const float*)d_in[8];
    float* out = (float*)d_out;

    dim3 pg(256, 8);
    proj_kernel<<<pg, NTHR>>>(x, WHw, WHb, 0);
    proj_kernel<<<pg, NTHR>>>(x, WCw, WCb, 1);
    rhn_seq_kernel<<<NCTA, NTHR>>>(RHw, RHb, RCw, RCb, out);
}